// round 5
// baseline (speedup 1.0000x reference)
#include <cuda_runtime.h>
#include <cuda_bf16.h>
#include <math.h>
#include <stdint.h>

#define T_TOKENS 4096
#define D_DIM    1024
#define H_DIM    2048
#define E_NUM    8

// ---------------- scratch (device globals; no runtime allocation) ----------
__device__ float g_probs[T_TOKENS * E_NUM];
__device__ float g_topval[T_TOKENS];
__device__ int   g_count[E_NUM];
__device__ int   g_toklist[E_NUM * T_TOKENS];
__device__ __nv_bfloat16 g_xb[T_TOKENS * D_DIM];          // x bf16 [T,D]
__device__ __nv_bfloat16 g_w1b[E_NUM * D_DIM * H_DIM];    // w1 bf16 [E][D][H]
__device__ __nv_bfloat16 g_w2b[E_NUM * H_DIM * D_DIM];    // w2 bf16 [E][H][D]
__device__ __nv_bfloat16 g_hb[T_TOKENS * H_DIM];          // hidden bf16 [T,H]
__device__ float g_y[T_TOKENS * D_DIM];                   // expert out * top_val

__device__ __forceinline__ float gelu_exact(float v) {
    return 0.5f * v * (1.0f + erff(v * 0.70710678118654752440f));
}

__device__ __forceinline__ uint32_t smem_u32(const void* p) {
    return (uint32_t)__cvta_generic_to_shared(p);
}

__device__ __forceinline__ void cp_async16(uint32_t dst, const void* src, int src_bytes) {
    asm volatile("cp.async.cg.shared.global [%0], [%1], 16, %2;\n"
                 :: "r"(dst), "l"(src), "r"(src_bytes));
}

__device__ __forceinline__ void ldsm_x4(uint32_t* r, uint32_t addr) {
    asm volatile("ldmatrix.sync.aligned.m8n8.x4.shared.b16 {%0,%1,%2,%3}, [%4];\n"
                 : "=r"(r[0]), "=r"(r[1]), "=r"(r[2]), "=r"(r[3]) : "r"(addr));
}

__device__ __forceinline__ void ldsm_x4_trans(uint32_t* r, uint32_t addr) {
    asm volatile("ldmatrix.sync.aligned.m8n8.x4.trans.shared.b16 {%0,%1,%2,%3}, [%4];\n"
                 : "=r"(r[0]), "=r"(r[1]), "=r"(r[2]), "=r"(r[3]) : "r"(addr));
}

__device__ __forceinline__ void mma_bf16(float* d, const uint32_t* a, uint32_t b0, uint32_t b1) {
    asm volatile("mma.sync.aligned.m16n8k16.row.col.f32.bf16.bf16.f32 "
                 "{%0,%1,%2,%3}, {%4,%5,%6,%7}, {%8,%9}, {%0,%1,%2,%3};\n"
                 : "+f"(d[0]), "+f"(d[1]), "+f"(d[2]), "+f"(d[3])
                 : "r"(a[0]), "r"(a[1]), "r"(a[2]), "r"(a[3]), "r"(b0), "r"(b1));
}

// ---------------- 0: zero counters ----------------
__global__ void zero_kernel() {
    if (threadIdx.x < E_NUM) g_count[threadIdx.x] = 0;
}

// ---------------- 0b: fp32 -> bf16 conversion ----------------
__global__ void convert_kernel(const float* __restrict__ src,
                               __nv_bfloat16* __restrict__ dst, int n) {
    int i = (blockIdx.x * blockDim.x + threadIdx.x) * 4;
    if (i < n) {
        float4 v = *(const float4*)(src + i);
        __nv_bfloat162* d = (__nv_bfloat162*)(dst + i);
        d[0] = __floats2bfloat162_rn(v.x, v.y);
        d[1] = __floats2bfloat162_rn(v.z, v.w);
    }
}

// ---------------- 1: gating ----------------
__global__ void gate_kernel(const float* __restrict__ x,
                            const float* __restrict__ gw,
                            const float* __restrict__ gb) {
    int t    = blockIdx.x;
    int tid  = threadIdx.x;
    int warp = tid >> 5;
    int lane = tid & 31;
    const float* xr = x + (size_t)t * D_DIM;
    float s = 0.f;
    #pragma unroll 4
    for (int d = lane; d < D_DIM; d += 32)
        s += xr[d] * gw[d * E_NUM + warp];
    #pragma unroll
    for (int o = 16; o > 0; o >>= 1) s += __shfl_xor_sync(0xffffffffu, s, o);
    __shared__ float logits[E_NUM];
    if (lane == 0) logits[warp] = s + gb[warp];
    __syncthreads();
    if (tid == 0) {
        float mx = logits[0];
        #pragma unroll
        for (int e = 1; e < E_NUM; e++) mx = fmaxf(mx, logits[e]);
        float p[E_NUM], den = 0.f;
        #pragma unroll
        for (int e = 0; e < E_NUM; e++) { p[e] = expf(logits[e] - mx); den += p[e]; }
        float inv = 1.f / den;
        float best = -1.f; int bi = 0;
        #pragma unroll
        for (int e = 0; e < E_NUM; e++) {
            p[e] *= inv;
            g_probs[t * E_NUM + e] = p[e];
            if (p[e] > best) { best = p[e]; bi = e; }
        }
        g_topval[t] = best;
        int slot = atomicAdd(&g_count[bi], 1);
        g_toklist[bi * T_TOKENS + slot] = t;
    }
}

// ---------------- 2/3: tensor-core gathered GEMM (3-stage, BN=256) ----------------
#define BM 128
#define BN 256
#define BK 32
#define STAGES 3
// dynamic smem layout (bytes)
#define A_ROWB  80             // 40 bf16 padded row (conflict-free ldmatrix)
#define B_ROWB  528            // 264 bf16 padded row (conflict-free trans ldmatrix)
#define A_ST    (128 * A_ROWB)         // 10240
#define B_ST    (32 * B_ROWB)          // 16896
#define A_OFF   0
#define B_OFF   (STAGES * A_ST)        // 30720
#define BIAS_OFF (B_OFF + STAGES * B_ST)  // 81408
#define SMEM_BYTES (BIAS_OFF + BN * 4)    // 82432

// EPI 0: h = gelu(acc + b1) -> g_hb bf16.   EPI 1: y = (acc + b2)*top_val -> g_y f32
template<int KDIM, int NDIM, int EPI>
__global__ __launch_bounds__(512)
void moe_gemm(const __nv_bfloat16* __restrict__ Aglob,
              const __nv_bfloat16* __restrict__ Wglob,
              const float* __restrict__ bias_glob) {
    const int e   = blockIdx.z;
    const int cnt = g_count[e];
    const int m0  = blockIdx.y * BM;
    if (m0 >= cnt) return;
    const int n0  = blockIdx.x * BN;
    const int* toks = g_toklist + e * T_TOKENS;
    const __nv_bfloat16* Bt = Wglob + (size_t)e * KDIM * NDIM;   // [K][N] row-major
    const float* bias = bias_glob + e * NDIM;

    extern __shared__ char dynsm[];
    const uint32_t sb = smem_u32(dynsm);
    float* sbias = (float*)(dynsm + BIAS_OFF);

    const int tid  = threadIdx.x;
    const int lane = tid & 31;
    const int wid  = tid >> 5;
    const int wm   = wid & 3;        // 4 m-slabs of 32 rows
    const int wn   = wid >> 2;       // 4 n-slabs of 64 cols

    if (tid < BN) sbias[tid] = bias[n0 + tid];

    // ---- A load mapping: 1 x 16B per thread ----
    const int a_row = tid >> 2;          // 0..127
    const int a_u   = tid & 3;           // 16B unit within 32-elem K chunk
    const int gm_a  = m0 + a_row;
    const bool a_ok = (gm_a < cnt);
    const int a_tok = a_ok ? toks[gm_a] : 0;
    const __nv_bfloat16* a_src = Aglob + (size_t)a_tok * KDIM + a_u * 8;
    const int a_bytes = a_ok ? 16 : 0;

    // ---- B load mapping: 2 x 16B per thread ----
    const int b_k  = tid >> 5;           // 0..15 (and +16)
    const int b_nu = tid & 31;           // 16B unit within 256-col row
    const __nv_bfloat16* b_src0 = Bt + (size_t)b_k * NDIM + n0 + b_nu * 8;
    const __nv_bfloat16* b_src1 = b_src0 + (size_t)16 * NDIM;

    uint32_t adst[STAGES], bdst0[STAGES], bdst1[STAGES];
    #pragma unroll
    for (int s = 0; s < STAGES; s++) {
        adst[s]  = sb + A_OFF + s * A_ST + a_row * A_ROWB + a_u * 16;
        bdst0[s] = sb + B_OFF + s * B_ST + b_k * B_ROWB + b_nu * 16;
        bdst1[s] = bdst0[s] + 16 * B_ROWB;
    }

    float acc[2][8][4];
    #pragma unroll
    for (int i = 0; i < 2; i++)
        #pragma unroll
        for (int j = 0; j < 8; j++)
            #pragma unroll
            for (int c = 0; c < 4; c++) acc[i][j][c] = 0.f;

    // prologue: stages 0,1
    #pragma unroll
    for (int st = 0; st < 2; st++) {
        cp_async16(adst[st], a_src + st * BK, a_bytes);
        cp_async16(bdst0[st], b_src0 + (size_t)st * BK * NDIM, 16);
        cp_async16(bdst1[st], b_src1 + (size_t)st * BK * NDIM, 16);
        asm volatile("cp.async.commit_group;\n");
    }

    const int NT = KDIM / BK;
    for (int s = 0; s < NT; s++) {
        asm volatile("cp.async.wait_group 1;\n");
        __syncthreads();

        const int buf = s % STAGES;
        const uint32_t abase = sb + A_OFF + buf * A_ST;
        const uint32_t bbase = sb + B_OFF + buf * B_ST;
        #pragma unroll
        for (int ks = 0; ks < 2; ks++) {
            uint32_t afr[2][4];
            #pragma unroll
            for (int mt = 0; mt < 2; mt++) {
                int row = wm * 32 + mt * 16 + (lane & 15);
                int col = ks * 16 + ((lane >> 4) << 3);
                ldsm_x4(afr[mt], abase + row * A_ROWB + col * 2);
            }
            uint32_t bfr[4][4];
            #pragma unroll
            for (int pr = 0; pr < 4; pr++) {
                int row = ks * 16 + (lane & 15);
                int col = wn * 64 + pr * 16 + ((lane >> 4) << 3);
                ldsm_x4_trans(bfr[pr], bbase + row * B_ROWB + col * 2);
            }
            #pragma unroll
            for (int mt = 0; mt < 2; mt++)
                #pragma unroll
                for (int nt = 0; nt < 8; nt++) {
                    int pr = nt >> 1;
                    int hb = (nt & 1) * 2;
                    mma_bf16(acc[mt][nt], afr[mt], bfr[pr][hb], bfr[pr][hb + 1]);
                }
        }
        __syncthreads();

        if (s + 2 < NT) {
            const int st = (s + 2) % STAGES;
            const int ko = (s + 2) * BK;
            cp_async16(adst[st], a_src + ko, a_bytes);
            cp_async16(bdst0[st], b_src0 + (size_t)ko * NDIM, 16);
            cp_async16(bdst1[st], b_src1 + (size_t)ko * NDIM, 16);
        }
        asm volatile("cp.async.commit_group;\n");
    }

    // ---- epilogue ----
    #pragma unroll
    for (int mt = 0; mt < 2; mt++) {
        int gm0 = m0 + wm * 32 + mt * 16 + (lane >> 2);
        int gm1 = gm0 + 8;
        bool ok0 = gm0 < cnt, ok1 = gm1 < cnt;
        int tok0 = ok0 ? toks[gm0] : 0;
        int tok1 = ok1 ? toks[gm1] : 0;
        float tv0 = 0.f, tv1 = 0.f;
        if (EPI == 1) {
            tv0 = ok0 ? g_topval[tok0] : 0.f;
            tv1 = ok1 ? g_topval[tok1] : 0.f;
        }
        #pragma unroll
        for (int nt = 0; nt < 8; nt++) {
            int lc = wn * 64 + nt * 8 + (lane & 3) * 2;   // local col in [0,256)
            float bv0 = sbias[lc], bv1 = sbias[lc + 1];
            float* a = acc[mt][nt];
            if (EPI == 0) {
                if (ok0) {
                    __nv_bfloat162 v = __floats2bfloat162_rn(
                        gelu_exact(a[0] + bv0), gelu_exact(a[1] + bv1));
                    *(__nv_bfloat162*)(g_hb + (size_t)tok0 * H_DIM + n0 + lc) = v;
                }
                if (ok1) {
                    __nv_bfloat162 v = __floats2bfloat162_rn(
                        gelu_exact(a[2] + bv0), gelu_exact(a[3] + bv1));
                    *(__nv_bfloat162*)(g_hb + (size_t)tok1 * H_DIM + n0 + lc) = v;
                }
            } else {
                if (ok0) {
                    float2 v = make_float2((a[0] + bv0) * tv0, (a[1] + bv1) * tv0);
                    *(float2*)(g_y + (size_t)tok0 * D_DIM + n0 + lc) = v;
                }
                if (ok1) {
                    float2 v = make_float2((a[2] + bv0) * tv1, (a[3] + bv1) * tv1);
                    *(float2*)(g_y + (size_t)tok1 * D_DIM + n0 + lc) = v;
                }
            }
        }
    }
}

// ---------------- 4: residual + L2-normalize + gamma*sqrt(D) + gelu ----------------
__global__ void finalize_kernel(const float* __restrict__ x,
                                const float* __restrict__ gamma,
                                float* __restrict__ out) {
    const int t   = blockIdx.x;
    const int tid = threadIdx.x;
    const float* xr = x  + (size_t)t * D_DIM;
    const float* er = g_y + (size_t)t * D_DIM;
    float yv[4];
    float ss = 0.f;
    #pragma unroll
    for (int i = 0; i < 4; i++) {
        int d = i * 256 + tid;
        float v = xr[d] + er[d];
        yv[i] = v;
        ss += v * v;
    }
    __shared__ float red[256];
    red[tid] = ss;
    __syncthreads();
    #pragma unroll
    for (int o = 128; o > 0; o >>= 1) {
        if (tid < o) red[tid] += red[tid + o];
        __syncthreads();
    }
    float nrm   = sqrtf(red[0]);
    float scale = 32.0f / fmaxf(nrm, 1e-12f);
    float* orow = out + (size_t)t * D_DIM;
    #pragma unroll
    for (int i = 0; i < 4; i++) {
        int d = i * 256 + tid;
        float v = yv[i] * scale * gamma[d];
        orow[d] = gelu_exact(v);
    }
}

// ---------------- 5: load-balance loss ----------------
__global__ void loss_kernel(float* __restrict__ out, int out_size) {
    __shared__ float red[256];
    __shared__ float imp[E_NUM];
    const int tid = threadIdx.x;
    for (int e = 0; e < E_NUM; e++) {
        float s = 0.f;
        for (int t = tid; t < T_TOKENS; t += 256)
            s += g_probs[t * E_NUM + e];
        red[tid] = s;
        __syncthreads();
        #pragma unroll
        for (int o = 128; o > 0; o >>= 1) {
            if (tid < o) red[tid] += red[tid + o];
            __syncthreads();
        }
        if (tid == 0) imp[e] = red[0];
        __syncthreads();
    }
    if (tid == 0) {
        float sum = 0.f;
        #pragma unroll
        for (int e = 0; e < E_NUM; e++) sum += imp[e];
        float mean = sum / (float)E_NUM;
        float var = 0.f;
        #pragma unroll
        for (int e = 0; e < E_NUM; e++) {
            float dlt = imp[e] - mean;
            var += dlt * dlt;
        }
        var /= (float)(E_NUM - 1);
        float loss = var / (mean * mean + 1e-10f);
        if (out_size > T_TOKENS * D_DIM)
            out[T_TOKENS * D_DIM] = loss;
    }
}

// ---------------- launch ----------------
extern "C" void kernel_launch(void* const* d_in, const int* in_sizes, int n_in,
                              void* d_out, int out_size) {
    const float* x     = (const float*)d_in[0];
    const float* gw    = (const float*)d_in[1];
    const float* gb    = (const float*)d_in[2];
    const float* w1    = (const float*)d_in[3];
    const float* b1    = (const float*)d_in[4];
    const float* w2    = (const float*)d_in[5];
    const float* b2    = (const float*)d_in[6];
    const float* gamma = (const float*)d_in[7];
    float* out = (float*)d_out;

    __nv_bfloat16 *xb, *w1b, *w2b, *hb;
    cudaGetSymbolAddress((void**)&xb,  g_xb);
    cudaGetSymbolAddress((void**)&w1b, g_w1b);
    cudaGetSymbolAddress((void**)&w2b, g_w2b);
    cudaGetSymbolAddress((void**)&hb,  g_hb);

    cudaFuncSetAttribute(moe_gemm<D_DIM, H_DIM, 0>,
                         cudaFuncAttributeMaxDynamicSharedMemorySize, SMEM_BYTES);
    cudaFuncSetAttribute(moe_gemm<H_DIM, D_DIM, 1>,
                         cudaFuncAttributeMaxDynamicSharedMemorySize, SMEM_BYTES);

    zero_kernel<<<1, 32>>>();
    {
        int n = T_TOKENS * D_DIM;
        convert_kernel<<<(n / 4 + 255) / 256, 256>>>(x, xb, n);
    }
    {
        int n = E_NUM * D_DIM * H_DIM;
        convert_kernel<<<(n / 4 + 255) / 256, 256>>>(w1, w1b, n);
        convert_kernel<<<(n / 4 + 255) / 256, 256>>>(w2, w2b, n);
    }
    gate_kernel<<<T_TOKENS, 256>>>(x, gw, gb);

    moe_gemm<D_DIM, H_DIM, 0>
        <<<dim3(H_DIM / BN, T_TOKENS / BM, E_NUM), 512, SMEM_BYTES>>>(xb, w1b, b1);
    moe_gemm<H_DIM, D_DIM, 1>
        <<<dim3(D_DIM / BN, T_TOKENS / BM, E_NUM), 512, SMEM_BYTES>>>(hb, w2b, b2);

    finalize_kernel<<<T_TOKENS, 256>>>(x, gamma, out);
    loss_kernel<<<1, 256>>>(out, out_size);
}

// round 6
// speedup vs baseline: 1.0202x; 1.0202x over previous
#include <cuda_runtime.h>
#include <cuda_bf16.h>
#include <math.h>
#include <stdint.h>

#define T_TOKENS 4096
#define D_DIM    1024
#define H_DIM    2048
#define E_NUM    8

// ---------------- scratch (device globals; no runtime allocation) ----------
__device__ float g_probs[T_TOKENS * E_NUM];
__device__ float g_topval[T_TOKENS];
__device__ int   g_count[E_NUM];
__device__ int   g_toklist[E_NUM * T_TOKENS];
__device__ __nv_bfloat16 g_xb[T_TOKENS * D_DIM];          // x bf16 [T,D]
__device__ __nv_bfloat16 g_w1b[E_NUM * D_DIM * H_DIM];    // w1 bf16 [E][D][H]
__device__ __nv_bfloat16 g_w2b[E_NUM * H_DIM * D_DIM];    // w2 bf16 [E][H][D]
__device__ __nv_bfloat16 g_hb[T_TOKENS * H_DIM];          // hidden bf16 [T,H]
__device__ float g_y[T_TOKENS * D_DIM];                   // expert out * top_val

__device__ __forceinline__ float gelu_exact(float v) {
    return 0.5f * v * (1.0f + erff(v * 0.70710678118654752440f));
}

__device__ __forceinline__ uint32_t smem_u32(const void* p) {
    return (uint32_t)__cvta_generic_to_shared(p);
}

__device__ __forceinline__ void cp_async16(uint32_t dst, const void* src, int src_bytes) {
    asm volatile("cp.async.cg.shared.global [%0], [%1], 16, %2;\n"
                 :: "r"(dst), "l"(src), "r"(src_bytes));
}

__device__ __forceinline__ void ldsm_x4(uint32_t* r, uint32_t addr) {
    asm volatile("ldmatrix.sync.aligned.m8n8.x4.shared.b16 {%0,%1,%2,%3}, [%4];\n"
                 : "=r"(r[0]), "=r"(r[1]), "=r"(r[2]), "=r"(r[3]) : "r"(addr));
}

__device__ __forceinline__ void ldsm_x4_trans(uint32_t* r, uint32_t addr) {
    asm volatile("ldmatrix.sync.aligned.m8n8.x4.trans.shared.b16 {%0,%1,%2,%3}, [%4];\n"
                 : "=r"(r[0]), "=r"(r[1]), "=r"(r[2]), "=r"(r[3]) : "r"(addr));
}

__device__ __forceinline__ void mma_bf16(float* d, const uint32_t* a, uint32_t b0, uint32_t b1) {
    asm volatile("mma.sync.aligned.m16n8k16.row.col.f32.bf16.bf16.f32 "
                 "{%0,%1,%2,%3}, {%4,%5,%6,%7}, {%8,%9}, {%0,%1,%2,%3};\n"
                 : "+f"(d[0]), "+f"(d[1]), "+f"(d[2]), "+f"(d[3])
                 : "r"(a[0]), "r"(a[1]), "r"(a[2]), "r"(a[3]), "r"(b0), "r"(b1));
}

// ---------------- 0: zero counters ----------------
__global__ void zero_kernel() {
    if (threadIdx.x < E_NUM) g_count[threadIdx.x] = 0;
}

// ---------------- 0b: fp32 -> bf16 conversion ----------------
__global__ void convert_kernel(const float* __restrict__ src,
                               __nv_bfloat16* __restrict__ dst, int n) {
    int i = (blockIdx.x * blockDim.x + threadIdx.x) * 4;
    if (i < n) {
        float4 v = *(const float4*)(src + i);
        __nv_bfloat162* d = (__nv_bfloat162*)(dst + i);
        d[0] = __floats2bfloat162_rn(v.x, v.y);
        d[1] = __floats2bfloat162_rn(v.z, v.w);
    }
}

// ---------------- 1: gating ----------------
__global__ void gate_kernel(const float* __restrict__ x,
                            const float* __restrict__ gw,
                            const float* __restrict__ gb) {
    int t    = blockIdx.x;
    int tid  = threadIdx.x;
    int warp = tid >> 5;
    int lane = tid & 31;
    const float* xr = x + (size_t)t * D_DIM;
    float s = 0.f;
    #pragma unroll 4
    for (int d = lane; d < D_DIM; d += 32)
        s += xr[d] * gw[d * E_NUM + warp];
    #pragma unroll
    for (int o = 16; o > 0; o >>= 1) s += __shfl_xor_sync(0xffffffffu, s, o);
    __shared__ float logits[E_NUM];
    if (lane == 0) logits[warp] = s + gb[warp];
    __syncthreads();
    if (tid == 0) {
        float mx = logits[0];
        #pragma unroll
        for (int e = 1; e < E_NUM; e++) mx = fmaxf(mx, logits[e]);
        float p[E_NUM], den = 0.f;
        #pragma unroll
        for (int e = 0; e < E_NUM; e++) { p[e] = expf(logits[e] - mx); den += p[e]; }
        float inv = 1.f / den;
        float best = -1.f; int bi = 0;
        #pragma unroll
        for (int e = 0; e < E_NUM; e++) {
            p[e] *= inv;
            g_probs[t * E_NUM + e] = p[e];
            if (p[e] > best) { best = p[e]; bi = e; }
        }
        g_topval[t] = best;
        int slot = atomicAdd(&g_count[bi], 1);
        g_toklist[bi * T_TOKENS + slot] = t;
    }
}

// ---------------- 2/3: tensor-core gathered GEMM (BK=64, 3-stage, BN=256) ----------------
#define BM 128
#define BN 256
#define BK 64
#define STAGES 3
// dynamic smem layout (bytes)
#define A_ROWB  144            // 64 bf16 (128B) padded to 144 -> conflict-free ldmatrix
#define B_ROWB  528            // 256 bf16 (512B) padded to 528 -> conflict-free trans ldmatrix
#define A_ST    (128 * A_ROWB)          // 18432
#define B_ST    (64 * B_ROWB)           // 33792
#define A_OFF   0
#define B_OFF   (STAGES * A_ST)         // 55296
#define BIAS_OFF (B_OFF + STAGES * B_ST)   // 156672
#define SMEM_BYTES (BIAS_OFF + BN * 4)     // 157696

// EPI 0: h = gelu(acc + b1) -> g_hb bf16.   EPI 1: y = (acc + b2)*top_val -> g_y f32
template<int KDIM, int NDIM, int EPI>
__global__ __launch_bounds__(512)
void moe_gemm(const __nv_bfloat16* __restrict__ Aglob,
              const __nv_bfloat16* __restrict__ Wglob,
              const float* __restrict__ bias_glob) {
    const int e   = blockIdx.z;
    const int cnt = g_count[e];
    const int m0  = blockIdx.y * BM;
    if (m0 >= cnt) return;
    const int n0  = blockIdx.x * BN;
    const int* toks = g_toklist + e * T_TOKENS;
    const __nv_bfloat16* Bt = Wglob + (size_t)e * KDIM * NDIM;   // [K][N] row-major
    const float* bias = bias_glob + e * NDIM;

    extern __shared__ char dynsm[];
    const uint32_t sb = smem_u32(dynsm);
    float* sbias = (float*)(dynsm + BIAS_OFF);

    const int tid  = threadIdx.x;
    const int lane = tid & 31;
    const int wid  = tid >> 5;
    const int wm   = wid & 3;        // 4 m-slabs of 32 rows
    const int wn   = wid >> 2;       // 4 n-slabs of 64 cols

    if (tid < BN) sbias[tid] = bias[n0 + tid];

    // ---- A load mapping: row = tid>>2, units (tid&3) and (tid&3)+4 ----
    const int a_row = tid >> 2;          // 0..127
    const int a_u   = tid & 3;
    const int gm_a  = m0 + a_row;
    const bool a_ok = (gm_a < cnt);
    const int a_tok = a_ok ? toks[gm_a] : 0;
    const __nv_bfloat16* a_src = Aglob + (size_t)a_tok * KDIM;
    const int a_bytes = a_ok ? 16 : 0;

    // ---- B load mapping: rows b_k + 16*i (i=0..3), unit tid&31 ----
    const int b_k  = tid >> 5;           // 0..15
    const int b_nu = tid & 31;           // 16B unit within 512B row
    const __nv_bfloat16* b_src[4];
    #pragma unroll
    for (int i = 0; i < 4; i++)
        b_src[i] = Bt + (size_t)(b_k + 16 * i) * NDIM + n0 + b_nu * 8;

    uint32_t adst[STAGES][2], bdst[STAGES][4];
    #pragma unroll
    for (int s = 0; s < STAGES; s++) {
        adst[s][0] = sb + A_OFF + s * A_ST + a_row * A_ROWB + a_u * 16;
        adst[s][1] = adst[s][0] + 64;    // unit +4
        #pragma unroll
        for (int i = 0; i < 4; i++)
            bdst[s][i] = sb + B_OFF + s * B_ST + (b_k + 16 * i) * B_ROWB + b_nu * 16;
    }

    float acc[2][8][4];
    #pragma unroll
    for (int i = 0; i < 2; i++)
        #pragma unroll
        for (int j = 0; j < 8; j++)
            #pragma unroll
            for (int c = 0; c < 4; c++) acc[i][j][c] = 0.f;

    // prologue: stages 0,1
    #pragma unroll
    for (int st = 0; st < 2; st++) {
        const int ko = st * BK;
        cp_async16(adst[st][0], a_src + ko + a_u * 8, a_bytes);
        cp_async16(adst[st][1], a_src + ko + (a_u + 4) * 8, a_bytes);
        #pragma unroll
        for (int i = 0; i < 4; i++)
            cp_async16(bdst[st][i], b_src[i] + (size_t)ko * NDIM, 16);
        asm volatile("cp.async.commit_group;\n");
    }

    const int NT = KDIM / BK;
    for (int s = 0; s < NT; s++) {
        asm volatile("cp.async.wait_group 1;\n");
        __syncthreads();

        const int buf = s % STAGES;
        const uint32_t abase = sb + A_OFF + buf * A_ST;
        const uint32_t bbase = sb + B_OFF + buf * B_ST;
        #pragma unroll
        for (int ks = 0; ks < 4; ks++) {
            uint32_t afr[2][4];
            #pragma unroll
            for (int mt = 0; mt < 2; mt++) {
                int row = wm * 32 + mt * 16 + (lane & 15);
                int colb = ks * 32 + ((lane >> 4) << 4);
                ldsm_x4(afr[mt], abase + row * A_ROWB + colb);
            }
            uint32_t bfr[4][4];
            #pragma unroll
            for (int pr = 0; pr < 4; pr++) {
                int row = ks * 16 + (lane & 15);
                int col = wn * 64 + pr * 16 + ((lane >> 4) << 3);
                ldsm_x4_trans(bfr[pr], bbase + row * B_ROWB + col * 2);
            }
            #pragma unroll
            for (int mt = 0; mt < 2; mt++)
                #pragma unroll
                for (int nt = 0; nt < 8; nt++) {
                    int pr = nt >> 1;
                    int hb = (nt & 1) * 2;
                    mma_bf16(acc[mt][nt], afr[mt], bfr[pr][hb], bfr[pr][hb + 1]);
                }
        }
        __syncthreads();

        if (s + 2 < NT) {
            const int st = (s + 2) % STAGES;
            const int ko = (s + 2) * BK;
            cp_async16(adst[st][0], a_src + ko + a_u * 8, a_bytes);
            cp_async16(adst[st][1], a_src + ko + (a_u + 4) * 8, a_bytes);
            #pragma unroll
            for (int i = 0; i < 4; i++)
                cp_async16(bdst[st][i], b_src[i] + (size_t)ko * NDIM, 16);
        }
        asm volatile("cp.async.commit_group;\n");
    }

    // ---- epilogue ----
    #pragma unroll
    for (int mt = 0; mt < 2; mt++) {
        int gm0 = m0 + wm * 32 + mt * 16 + (lane >> 2);
        int gm1 = gm0 + 8;
        bool ok0 = gm0 < cnt, ok1 = gm1 < cnt;
        int tok0 = ok0 ? toks[gm0] : 0;
        int tok1 = ok1 ? toks[gm1] : 0;
        float tv0 = 0.f, tv1 = 0.f;
        if (EPI == 1) {
            tv0 = ok0 ? g_topval[tok0] : 0.f;
            tv1 = ok1 ? g_topval[tok1] : 0.f;
        }
        #pragma unroll
        for (int nt = 0; nt < 8; nt++) {
            int lc = wn * 64 + nt * 8 + (lane & 3) * 2;   // local col in [0,256)
            float bv0 = sbias[lc], bv1 = sbias[lc + 1];
            float* a = acc[mt][nt];
            if (EPI == 0) {
                if (ok0) {
                    __nv_bfloat162 v = __floats2bfloat162_rn(
                        gelu_exact(a[0] + bv0), gelu_exact(a[1] + bv1));
                    *(__nv_bfloat162*)(g_hb + (size_t)tok0 * H_DIM + n0 + lc) = v;
                }
                if (ok1) {
                    __nv_bfloat162 v = __floats2bfloat162_rn(
                        gelu_exact(a[2] + bv0), gelu_exact(a[3] + bv1));
                    *(__nv_bfloat162*)(g_hb + (size_t)tok1 * H_DIM + n0 + lc) = v;
                }
            } else {
                if (ok0) {
                    float2 v = make_float2((a[0] + bv0) * tv0, (a[1] + bv1) * tv0);
                    *(float2*)(g_y + (size_t)tok0 * D_DIM + n0 + lc) = v;
                }
                if (ok1) {
                    float2 v = make_float2((a[2] + bv0) * tv1, (a[3] + bv1) * tv1);
                    *(float2*)(g_y + (size_t)tok1 * D_DIM + n0 + lc) = v;
                }
            }
        }
    }
}

// ---------------- 4: residual + L2-normalize + gamma*sqrt(D) + gelu ----------------
__global__ void finalize_kernel(const float* __restrict__ x,
                                const float* __restrict__ gamma,
                                float* __restrict__ out) {
    const int t   = blockIdx.x;
    const int tid = threadIdx.x;
    const float* xr = x  + (size_t)t * D_DIM;
    const float* er = g_y + (size_t)t * D_DIM;
    float yv[4];
    float ss = 0.f;
    #pragma unroll
    for (int i = 0; i < 4; i++) {
        int d = i * 256 + tid;
        float v = xr[d] + er[d];
        yv[i] = v;
        ss += v * v;
    }
    __shared__ float red[256];
    red[tid] = ss;
    __syncthreads();
    #pragma unroll
    for (int o = 128; o > 0; o >>= 1) {
        if (tid < o) red[tid] += red[tid + o];
        __syncthreads();
    }
    float nrm   = sqrtf(red[0]);
    float scale = 32.0f / fmaxf(nrm, 1e-12f);
    float* orow = out + (size_t)t * D_DIM;
    #pragma unroll
    for (int i = 0; i < 4; i++) {
        int d = i * 256 + tid;
        float v = yv[i] * scale * gamma[d];
        orow[d] = gelu_exact(v);
    }
}

// ---------------- 5: load-balance loss ----------------
__global__ void loss_kernel(float* __restrict__ out, int out_size) {
    __shared__ float red[256];
    __shared__ float imp[E_NUM];
    const int tid = threadIdx.x;
    for (int e = 0; e < E_NUM; e++) {
        float s = 0.f;
        for (int t = tid; t < T_TOKENS; t += 256)
            s += g_probs[t * E_NUM + e];
        red[tid] = s;
        __syncthreads();
        #pragma unroll
        for (int o = 128; o > 0; o >>= 1) {
            if (tid < o) red[tid] += red[tid + o];
            __syncthreads();
        }
        if (tid == 0) imp[e] = red[0];
        __syncthreads();
    }
    if (tid == 0) {
        float sum = 0.f;
        #pragma unroll
        for (int e = 0; e < E_NUM; e++) sum += imp[e];
        float mean = sum / (float)E_NUM;
        float var = 0.f;
        #pragma unroll
        for (int e = 0; e < E_NUM; e++) {
            float dlt = imp[e] - mean;
            var += dlt * dlt;
        }
        var /= (float)(E_NUM - 1);
        float loss = var / (mean * mean + 1e-10f);
        if (out_size > T_TOKENS * D_DIM)
            out[T_TOKENS * D_DIM] = loss;
    }
}

// ---------------- launch (stream fork/join, graph-capturable) ----------------
extern "C" void kernel_launch(void* const* d_in, const int* in_sizes, int n_in,
                              void* d_out, int out_size) {
    const float* x     = (const float*)d_in[0];
    const float* gw    = (const float*)d_in[1];
    const float* gb    = (const float*)d_in[2];
    const float* w1    = (const float*)d_in[3];
    const float* b1    = (const float*)d_in[4];
    const float* w2    = (const float*)d_in[5];
    const float* b2    = (const float*)d_in[6];
    const float* gamma = (const float*)d_in[7];
    float* out = (float*)d_out;

    __nv_bfloat16 *xb, *w1b, *w2b, *hb;
    cudaGetSymbolAddress((void**)&xb,  g_xb);
    cudaGetSymbolAddress((void**)&w1b, g_w1b);
    cudaGetSymbolAddress((void**)&w2b, g_w2b);
    cudaGetSymbolAddress((void**)&hb,  g_hb);

    static bool init_done = false;
    static cudaStream_t s1, s2;
    static cudaEvent_t ev_fork, ev_w1, ev_w2;
    if (!init_done) {
        cudaStreamCreateWithFlags(&s1, cudaStreamNonBlocking);
        cudaStreamCreateWithFlags(&s2, cudaStreamNonBlocking);
        cudaEventCreateWithFlags(&ev_fork, cudaEventDisableTiming);
        cudaEventCreateWithFlags(&ev_w1,   cudaEventDisableTiming);
        cudaEventCreateWithFlags(&ev_w2,   cudaEventDisableTiming);
        cudaFuncSetAttribute(moe_gemm<D_DIM, H_DIM, 0>,
                             cudaFuncAttributeMaxDynamicSharedMemorySize, SMEM_BYTES);
        cudaFuncSetAttribute(moe_gemm<H_DIM, D_DIM, 1>,
                             cudaFuncAttributeMaxDynamicSharedMemorySize, SMEM_BYTES);
        init_done = true;
    }

    const int nw = E_NUM * D_DIM * H_DIM;

    // fork: weight converts on side streams
    cudaEventRecord(ev_fork, 0);
    cudaStreamWaitEvent(s1, ev_fork, 0);
    cudaStreamWaitEvent(s2, ev_fork, 0);
    convert_kernel<<<(nw / 4 + 255) / 256, 256, 0, s1>>>(w1, w1b, nw);
    convert_kernel<<<(nw / 4 + 255) / 256, 256, 0, s2>>>(w2, w2b, nw);
    cudaEventRecord(ev_w1, s1);
    cudaEventRecord(ev_w2, s2);

    // main stream: routing-side chain
    zero_kernel<<<1, 32>>>();
    {
        int n = T_TOKENS * D_DIM;
        convert_kernel<<<(n / 4 + 255) / 256, 256>>>(x, xb, n);
    }
    gate_kernel<<<T_TOKENS, 256>>>(x, gw, gb);

    // join w1, run GEMM1
    cudaStreamWaitEvent(0, ev_w1, 0);
    moe_gemm<D_DIM, H_DIM, 0>
        <<<dim3(H_DIM / BN, T_TOKENS / BM, E_NUM), 512, SMEM_BYTES>>>(xb, w1b, b1);

    // join w2, run GEMM2
    cudaStreamWaitEvent(0, ev_w2, 0);
    moe_gemm<H_DIM, D_DIM, 1>
        <<<dim3(D_DIM / BN, T_TOKENS / BM, E_NUM), 512, SMEM_BYTES>>>(hb, w2b, b2);

    finalize_kernel<<<T_TOKENS, 256>>>(x, gamma, out);
    loss_kernel<<<1, 256>>>(out, out_size);
}